// round 7
// baseline (speedup 1.0000x reference)
#include <cuda_runtime.h>
#include <cuda_bf16.h>
#include <cstdint>

// ---------------------------------------------------------------------------
// GatedExpertsEncoder (sm_103a, legacy mma.sync path — tcgen05 not available
// through this toolchain's compute_103 PTX stage).
// out = sum_e w[:,e] * act(X @ W_e + b_e), 3 layers, E=8 soft MoE.
// bf16 split precision (ah*bh + ah*bl + al*bh), fp32 accumulate m16n8k16.
// X and W pre-split into bf16 hi/lo globals; mainloop = cp.async + ldmatrix +
// MMA only. Per-expert register partials folded with w_e at e-boundaries.
// ---------------------------------------------------------------------------

static constexpr int BATCH = 65536;
static constexpr int DIN   = 512;
static constexpr int DH    = 512;
static constexpr int EXPN  = 8;
static constexpr int KTOT  = EXPN * DIN;   // 4096

static constexpr int BM = 128, BN = 128, BK = 64;
static constexpr int NIT = KTOT / BK;      // 64

// smem rows: 64 bf16 = 128B data + 16B pad = 144B stride (LDSM ptrs r*36w mod32
// distinct; cp.async 16B-aligned).
static constexpr int RSTRB = 144;
static constexpr int TILEB = 128 * RSTRB;          // 18432 B
static constexpr int OFF_AL = TILEB;
static constexpr int OFF_BH = 2 * TILEB;
static constexpr int OFF_BL = 3 * TILEB;
static constexpr int STAGE  = 4 * TILEB;           // 73728 B
static constexpr int WSM_OFF = 2 * STAGE;          // 147456 (128*8 fp32)
static constexpr int BSM_OFF = WSM_OFF + 4096;     // 151552 (8*128 fp32)
static constexpr int SMEM_BYTES = BSM_OFF + 4096;  // 155648

// ------------------------------ scratch -----------------------------------
__device__ __align__(16) float g_w [(size_t)BATCH * EXPN];
__device__ __align__(16) __nv_bfloat16 g_xah[(size_t)BATCH * DIN];
__device__ __align__(16) __nv_bfloat16 g_xal[(size_t)BATCH * DIN];
__device__ __align__(16) __nv_bfloat16 g_xbh[(size_t)BATCH * DIN];
__device__ __align__(16) __nv_bfloat16 g_xbl[(size_t)BATCH * DIN];
__device__ __align__(16) __nv_bfloat16 g_wth[(size_t)3 * DH * KTOT];
__device__ __align__(16) __nv_bfloat16 g_wtl[(size_t)3 * DH * KTOT];

// ------------------------------ helpers -----------------------------------
__device__ __forceinline__ float eluf(float x) { return x > 0.f ? x : expm1f(x); }

__device__ __forceinline__ uint32_t packbf2(float vlo, float vhi) {
    uint32_t r;
    asm("cvt.rn.bf16x2.f32 %0, %1, %2;" : "=r"(r) : "f"(vhi), "f"(vlo));
    return r;
}
__device__ __forceinline__ void splitbf2(float v0, float v1, uint32_t& hi, uint32_t& lo) {
    hi = packbf2(v0, v1);
    float h0 = __uint_as_float(hi << 16);
    float h1 = __uint_as_float(hi & 0xFFFF0000u);
    lo = packbf2(v0 - h0, v1 - h1);
}
__device__ __forceinline__ uint32_t smem_u32(const void* p) {
    uint32_t a;
    asm("{ .reg .u64 t; cvta.to.shared.u64 t, %1; cvt.u32.u64 %0, t; }" : "=r"(a) : "l"(p));
    return a;
}
__device__ __forceinline__ void cp16(uint32_t dst, const void* src) {
    asm volatile("cp.async.cg.shared.global [%0], [%1], 16;" :: "r"(dst), "l"(src) : "memory");
}
__device__ __forceinline__ void ldsm4(uint32_t r[4], uint32_t addr) {
    asm volatile("ldmatrix.sync.aligned.m8n8.x4.shared.b16 {%0,%1,%2,%3}, [%4];"
                 : "=r"(r[0]), "=r"(r[1]), "=r"(r[2]), "=r"(r[3]) : "r"(addr));
}
__device__ __forceinline__ void mma_bf16(float c[4], const uint32_t a[4], const uint32_t b[2]) {
    asm volatile(
        "mma.sync.aligned.m16n8k16.row.col.f32.bf16.bf16.f32 "
        "{%0,%1,%2,%3}, {%4,%5,%6,%7}, {%8,%9}, {%0,%1,%2,%3};\n"
        : "+f"(c[0]), "+f"(c[1]), "+f"(c[2]), "+f"(c[3])
        : "r"(a[0]), "r"(a[1]), "r"(a[2]), "r"(a[3]), "r"(b[0]), "r"(b[1]));
}

// ---------------------------------------------------------------------------
// Gating MLP (proven since R3).
// ---------------------------------------------------------------------------
__global__ void gating_kernel(const float* __restrict__ z,
                              const void* __restrict__ idx_raw,
                              const float* __restrict__ Wg1, const float* __restrict__ bg1,
                              const float* __restrict__ Wg2, const float* __restrict__ bg2,
                              const float* __restrict__ Wg3, const float* __restrict__ bg3)
{
    __shared__ float bufA[8][128];
    __shared__ float bufB[8][128];
    const int warp = threadIdx.x >> 5;
    const int lane = threadIdx.x & 31;
    const int gwarp = blockIdx.x * 8 + warp;
    const int nwarp = gridDim.x * 8;

    const int* idx32 = (const int*)idx_raw;
    const bool is64 = (idx32[1] == 0);

    for (int row = gwarp; row < BATCH; row += nwarp) {
        const float* zr = z + (size_t)row * DIN;
        for (int k = lane; k < 128; k += 32) {
            int col = is64 ? idx32[2 * k] : idx32[k];
            bufA[warp][k] = zr[col & (DIN - 1)];
        }
        __syncwarp();
        {
            float s0 = bg1[lane * 4 + 0], s1 = bg1[lane * 4 + 1];
            float s2 = bg1[lane * 4 + 2], s3 = bg1[lane * 4 + 3];
            #pragma unroll 8
            for (int k = 0; k < 128; ++k) {
                float xk = bufA[warp][k];
                float4 wv = *(const float4*)(Wg1 + k * 128 + lane * 4);
                s0 = fmaf(xk, wv.x, s0); s1 = fmaf(xk, wv.y, s1);
                s2 = fmaf(xk, wv.z, s2); s3 = fmaf(xk, wv.w, s3);
            }
            bufB[warp][lane * 4 + 0] = eluf(s0);
            bufB[warp][lane * 4 + 1] = eluf(s1);
            bufB[warp][lane * 4 + 2] = eluf(s2);
            bufB[warp][lane * 4 + 3] = eluf(s3);
        }
        __syncwarp();
        {
            float s0 = bg2[lane * 4 + 0], s1 = bg2[lane * 4 + 1];
            float s2 = bg2[lane * 4 + 2], s3 = bg2[lane * 4 + 3];
            #pragma unroll 8
            for (int k = 0; k < 128; ++k) {
                float xk = bufB[warp][k];
                float4 wv = *(const float4*)(Wg2 + k * 128 + lane * 4);
                s0 = fmaf(xk, wv.x, s0); s1 = fmaf(xk, wv.y, s1);
                s2 = fmaf(xk, wv.z, s2); s3 = fmaf(xk, wv.w, s3);
            }
            bufA[warp][lane * 4 + 0] = eluf(s0);
            bufA[warp][lane * 4 + 1] = eluf(s1);
            bufA[warp][lane * 4 + 2] = eluf(s2);
            bufA[warp][lane * 4 + 3] = eluf(s3);
        }
        __syncwarp();
        if (lane < 8) {
            float s = bg3[lane];
            #pragma unroll 8
            for (int k = 0; k < 128; ++k)
                s = fmaf(bufA[warp][k], Wg3[k * 8 + lane], s);
            g_w[(size_t)row * 8 + lane] = s;
        }
        __syncwarp();
    }
}

// ---------------------------------------------------------------------------
// W pre-transpose+split: W[k=4096][o=512] fp32 -> Wt hi/lo [o=512][k=4096] bf16
// ---------------------------------------------------------------------------
__global__ void wsplit_kernel(const float* __restrict__ W, int layer)
{
    __shared__ float T[32][33];
    __nv_bfloat16* oh = g_wth + (size_t)layer * DH * KTOT;
    __nv_bfloat16* ol = g_wtl + (size_t)layer * DH * KTOT;
    const int kt = blockIdx.x * 32, ot = blockIdx.y * 32;
    const int tx = threadIdx.x, ty = threadIdx.y;   // 32 x 8
    #pragma unroll
    for (int i = 0; i < 4; ++i)
        T[ty + 8 * i][tx] = W[(size_t)(kt + ty + 8 * i) * DH + ot + tx];
    __syncthreads();
    #pragma unroll
    for (int i = 0; i < 4; ++i) {
        const int o = ot + ty + 8 * i, k = kt + tx;
        float v = T[tx][ty + 8 * i];
        __nv_bfloat16 h = __float2bfloat16(v);
        oh[(size_t)o * KTOT + k] = h;
        ol[(size_t)o * KTOT + k] = __float2bfloat16(v - __bfloat162float(h));
    }
}

// ---------------------------------------------------------------------------
// z -> split bf16 hi/lo (layer-1 input)
// ---------------------------------------------------------------------------
__global__ void splitz_kernel(const float* __restrict__ z)
{
    const size_t i = (size_t)(blockIdx.x * blockDim.x + threadIdx.x);
    const size_t n4 = (size_t)BATCH * DIN / 4;
    if (i >= n4) return;
    float4 v = ((const float4*)z)[i];
    uint32_t h0, l0, h1, l1;
    splitbf2(v.x, v.y, h0, l0);
    splitbf2(v.z, v.w, h1, l1);
    ((uint2*)g_xah)[i] = make_uint2(h0, h1);
    ((uint2*)g_xal)[i] = make_uint2(l0, l1);
}

// ---------------------------------------------------------------------------
// Layer kernel: CTA 128x128, 512 threads, 16 warps (4m x 4n, warp tile 32x32),
// BK=64 double-buffered, pure cp.async operand staging.
// MODE 0: Xa -> Xb split; MODE 1: Xb -> Xa split; MODE 2: Xa -> fp32 out.
// ---------------------------------------------------------------------------
template <bool ACT, int MODE>
__global__ __launch_bounds__(512, 1)
void layer_mm(const float* __restrict__ bias, float* __restrict__ Yp)
{
    const __nv_bfloat16* Xh = (MODE == 1) ? g_xbh : g_xah;
    const __nv_bfloat16* Xl = (MODE == 1) ? g_xbl : g_xal;
    const __nv_bfloat16* Wth = g_wth + (size_t)MODE * DH * KTOT;
    const __nv_bfloat16* Wtl = g_wtl + (size_t)MODE * DH * KTOT;

    extern __shared__ char sm[];
    const uint32_t sb = smem_u32(sm);
    float* wsm = (float*)(sm + WSM_OFF);
    float* bsm = (float*)(sm + BSM_OFF);

    const int tid  = threadIdx.x;
    const int lane = tid & 31;
    const int warp = tid >> 5;
    const int g = lane >> 2, t = lane & 3;
    const int wm = warp >> 2, wn = warp & 3;        // 4 x 4 warps, tile 32x32
    const int mBase = blockIdx.y * BM;
    const int nBase = blockIdx.x * BN;

    for (int i = tid; i < BM * EXPN; i += 512) wsm[i] = g_w[(size_t)mBase * EXPN + i];
    for (int i = tid; i < EXPN * BN; i += 512) bsm[i] = bias[(i >> 7) * DH + nBase + (i & 127)];

    float part[2][4][4], tot[2][4][4];
    #pragma unroll
    for (int mt = 0; mt < 2; ++mt)
        #pragma unroll
        for (int nf = 0; nf < 4; ++nf)
            #pragma unroll
            for (int q = 0; q < 4; ++q) { part[mt][nf][q] = 0.f; tot[mt][nf][q] = 0.f; }

    // ldmatrix per-thread base offsets (stage-relative)
    const uint32_t a_off = (uint32_t)(wm * 32 + (lane & 15)) * RSTRB + ((lane >> 4) & 1) * 16;
    const uint32_t b_off = (uint32_t)(wn * 32 + (lane & 7) + ((lane & 16) >> 1)) * RSTRB
                         + ((lane >> 3) & 1) * 16;

    auto cpAB = [&](int it, int buf) {
        const uint32_t base = sb + buf * STAGE;
        const int i0 = (it & 7) * BK;
        #pragma unroll
        for (int u = 0; u < 2; ++u) {
            int j = tid + 512 * u;
            int r = j >> 3, c = j & 7;
            uint32_t d = (uint32_t)(r * RSTRB + c * 16);
            const size_t so = (size_t)(mBase + r) * DIN + i0 + c * 8;
            cp16(base + d, Xh + so);
            cp16(base + OFF_AL + d, Xl + so);
        }
        const size_t ko = (size_t)it * BK;
        #pragma unroll
        for (int u = 0; u < 2; ++u) {
            int j = tid + 512 * u;
            int n = j >> 3, c = j & 7;
            uint32_t d = (uint32_t)(n * RSTRB + c * 16);
            const size_t so = (size_t)(nBase + n) * KTOT + ko + c * 8;
            cp16(base + OFF_BH + d, Wth + so);
            cp16(base + OFF_BL + d, Wtl + so);
        }
    };

    // prologue
    cpAB(0, 0);
    asm volatile("cp.async.commit_group;" ::: "memory");
    asm volatile("cp.async.wait_group 0;" ::: "memory");
    __syncthreads();

    for (int it = 0; it < NIT; ++it) {
        const int cur = it & 1, nxt = cur ^ 1;
        const bool more = (it + 1) < NIT;
        if (more) {
            cpAB(it + 1, nxt);
            asm volatile("cp.async.commit_group;" ::: "memory");
        }

        const uint32_t st = sb + cur * STAGE;
        #pragma unroll
        for (int ks = 0; ks < 4; ++ks) {
            uint32_t ah[2][4], al[2][4], bh[2][4], bl[2][4];
            #pragma unroll
            for (int mt = 0; mt < 2; ++mt) {
                uint32_t ao = st + a_off + mt * (16 * RSTRB) + ks * 32;
                ldsm4(ah[mt], ao);
                ldsm4(al[mt], ao + OFF_AL);
            }
            #pragma unroll
            for (int p = 0; p < 2; ++p) {
                uint32_t bo = st + OFF_BH + b_off + p * (16 * RSTRB) + ks * 32;
                ldsm4(bh[p], bo);
                ldsm4(bl[p], bo + TILEB);
            }
            // product-major: same-acc reuse distance = 8 MMAs
            #pragma unroll
            for (int mt = 0; mt < 2; ++mt)
                #pragma unroll
                for (int nf = 0; nf < 4; ++nf)
                    mma_bf16(part[mt][nf], ah[mt], &bh[nf >> 1][(nf & 1) * 2]);
            #pragma unroll
            for (int mt = 0; mt < 2; ++mt)
                #pragma unroll
                for (int nf = 0; nf < 4; ++nf)
                    mma_bf16(part[mt][nf], ah[mt], &bl[nf >> 1][(nf & 1) * 2]);
            #pragma unroll
            for (int mt = 0; mt < 2; ++mt)
                #pragma unroll
                for (int nf = 0; nf < 4; ++nf)
                    mma_bf16(part[mt][nf], al[mt], &bh[nf >> 1][(nf & 1) * 2]);
        }

        if ((it & 7) == 7) {   // expert boundary: fold partial with w_e
            const int e = it >> 3;
            #pragma unroll
            for (int mt = 0; mt < 2; ++mt) {
                const int r0 = wm * 32 + mt * 16 + g;
                const float w0 = wsm[r0 * 8 + e];
                const float w1 = wsm[(r0 + 8) * 8 + e];
                #pragma unroll
                for (int nf = 0; nf < 4; ++nf) {
                    tot[mt][nf][0] = fmaf(w0, part[mt][nf][0], tot[mt][nf][0]);
                    tot[mt][nf][1] = fmaf(w0, part[mt][nf][1], tot[mt][nf][1]);
                    tot[mt][nf][2] = fmaf(w1, part[mt][nf][2], tot[mt][nf][2]);
                    tot[mt][nf][3] = fmaf(w1, part[mt][nf][3], tot[mt][nf][3]);
                    part[mt][nf][0] = 0.f; part[mt][nf][1] = 0.f;
                    part[mt][nf][2] = 0.f; part[mt][nf][3] = 0.f;
                }
            }
        }

        asm volatile("cp.async.wait_group 0;" ::: "memory");
        __syncthreads();
    }

    // epilogue: + w @ bias, activation, store (split bf16 for MODE<2)
    #pragma unroll
    for (int mt = 0; mt < 2; ++mt) {
        const int r0 = wm * 32 + mt * 16 + g;
        float w0[8], w1[8];
        #pragma unroll
        for (int e = 0; e < 8; ++e) {
            w0[e] = wsm[r0 * 8 + e];
            w1[e] = wsm[(r0 + 8) * 8 + e];
        }
        #pragma unroll
        for (int nf = 0; nf < 4; ++nf) {
            const int c = wn * 32 + nf * 8 + t * 2;
            float b00 = 0.f, b01 = 0.f, b10 = 0.f, b11 = 0.f;
            #pragma unroll
            for (int e = 0; e < 8; ++e) {
                float be0 = bsm[e * 128 + c], be1 = bsm[e * 128 + c + 1];
                b00 = fmaf(w0[e], be0, b00); b01 = fmaf(w0[e], be1, b01);
                b10 = fmaf(w1[e], be0, b10); b11 = fmaf(w1[e], be1, b11);
            }
            float v0 = tot[mt][nf][0] + b00;
            float v1 = tot[mt][nf][1] + b01;
            float v2 = tot[mt][nf][2] + b10;
            float v3 = tot[mt][nf][3] + b11;
            if (ACT) { v0 = eluf(v0); v1 = eluf(v1); v2 = eluf(v2); v3 = eluf(v3); }
            const size_t o0 = (size_t)(mBase + r0) * DH + nBase + c;
            const size_t o1 = (size_t)(mBase + r0 + 8) * DH + nBase + c;
            if (MODE == 2) {
                *(float2*)(Yp + o0) = make_float2(v0, v1);
                *(float2*)(Yp + o1) = make_float2(v2, v3);
            } else {
                __nv_bfloat16* oh = (MODE == 0) ? g_xbh : g_xah;
                __nv_bfloat16* ol = (MODE == 0) ? g_xbl : g_xal;
                uint32_t h0, l0, h1, l1;
                splitbf2(v0, v1, h0, l0);
                splitbf2(v2, v3, h1, l1);
                *(uint32_t*)(oh + o0) = h0;
                *(uint32_t*)(ol + o0) = l0;
                *(uint32_t*)(oh + o1) = h1;
                *(uint32_t*)(ol + o1) = l1;
            }
        }
    }
}

// ---------------------------------------------------------------------------
extern "C" void kernel_launch(void* const* d_in, const int* in_sizes, int n_in,
                              void* d_out, int out_size)
{
    const float* z   = (const float*)d_in[0];
    const void*  idx = (const void*)d_in[1];
    const float* Wg1 = (const float*)d_in[2];
    const float* bg1 = (const float*)d_in[3];
    const float* Wg2 = (const float*)d_in[4];
    const float* bg2 = (const float*)d_in[5];
    const float* Wg3 = (const float*)d_in[6];
    const float* bg3 = (const float*)d_in[7];
    const float* W1  = (const float*)d_in[8];
    const float* b1  = (const float*)d_in[9];
    const float* W2  = (const float*)d_in[10];
    const float* b2  = (const float*)d_in[11];
    const float* W3  = (const float*)d_in[12];
    const float* b3  = (const float*)d_in[13];
    float* out = (float*)d_out;

    cudaFuncSetAttribute(layer_mm<true , 0>, cudaFuncAttributeMaxDynamicSharedMemorySize, SMEM_BYTES);
    cudaFuncSetAttribute(layer_mm<true , 1>, cudaFuncAttributeMaxDynamicSharedMemorySize, SMEM_BYTES);
    cudaFuncSetAttribute(layer_mm<false, 2>, cudaFuncAttributeMaxDynamicSharedMemorySize, SMEM_BYTES);

    gating_kernel<<<1024, 256>>>(z, idx, Wg1, bg1, Wg2, bg2, Wg3, bg3);

    dim3 wgrid(KTOT / 32, DH / 32);   // (128, 16)
    dim3 wblk(32, 8);
    wsplit_kernel<<<wgrid, wblk>>>(W1, 0);
    wsplit_kernel<<<wgrid, wblk>>>(W2, 1);
    wsplit_kernel<<<wgrid, wblk>>>(W3, 2);

    splitz_kernel<<<(BATCH * DIN / 4 + 255) / 256, 256>>>(z);

    dim3 grid(DH / BN, BATCH / BM);   // (4, 512)
    layer_mm<true , 0><<<grid, 512, SMEM_BYTES>>>(b1, nullptr);
    layer_mm<true , 1><<<grid, 512, SMEM_BYTES>>>(b2, nullptr);
    layer_mm<false, 2><<<grid, 512, SMEM_BYTES>>>(b3, out);
}

// round 8
// speedup vs baseline: 1.1697x; 1.1697x over previous
#include <cuda_runtime.h>
#include <cuda_bf16.h>
#include <cstdint>

// ---------------------------------------------------------------------------
// GatedExpertsEncoder (sm_103a, legacy mma.sync path — tcgen05 not available
// through this toolchain's compute_103 PTX stage).
// out = sum_e w[:,e] * act(X @ W_e + b_e), 3 layers, E=8 soft MoE.
// bf16 split precision (ah*bh + ah*bl + al*bh), fp32 accumulate m16n8k16.
// X and W pre-split into bf16 hi/lo globals; mainloop = cp.async + ldmatrix +
// MMA. Per-expert register partials folded with w_e at expert boundaries.
// R8: SW128-swizzled smem (no padding), 3-stage cp.async pipeline, wait_group 1.
// ---------------------------------------------------------------------------

static constexpr int BATCH = 65536;
static constexpr int DIN   = 512;
static constexpr int DH    = 512;
static constexpr int EXPN  = 8;
static constexpr int KTOT  = EXPN * DIN;   // 4096

static constexpr int BM = 128, BN = 128, BK = 64;
static constexpr int NIT = KTOT / BK;      // 64
static constexpr int NSTAGE = 3;

// swizzled tiles: 128 rows x 128B, no padding
static constexpr int TILEB  = 128 * 128;            // 16384 B
static constexpr int OFF_AL = TILEB;                // 16384
static constexpr int OFF_BH = 2 * TILEB;            // 32768
static constexpr int OFF_BL = 3 * TILEB;            // 49152
static constexpr int STAGE  = 4 * TILEB;            // 65536 B
static constexpr int WSM_OFF = NSTAGE * STAGE;      // 196608 (128*8 fp32)
static constexpr int BSM_OFF = WSM_OFF + 4096;      // 200704 (8*128 fp32)
static constexpr int SMEM_BYTES = BSM_OFF + 4096;   // 204800

// ------------------------------ scratch -----------------------------------
__device__ __align__(16) float g_w [(size_t)BATCH * EXPN];
__device__ __align__(16) __nv_bfloat16 g_xah[(size_t)BATCH * DIN];
__device__ __align__(16) __nv_bfloat16 g_xal[(size_t)BATCH * DIN];
__device__ __align__(16) __nv_bfloat16 g_xbh[(size_t)BATCH * DIN];
__device__ __align__(16) __nv_bfloat16 g_xbl[(size_t)BATCH * DIN];
__device__ __align__(16) __nv_bfloat16 g_wth[(size_t)3 * DH * KTOT];
__device__ __align__(16) __nv_bfloat16 g_wtl[(size_t)3 * DH * KTOT];

// ------------------------------ helpers -----------------------------------
__device__ __forceinline__ float eluf(float x) { return x > 0.f ? x : expm1f(x); }

__device__ __forceinline__ uint32_t packbf2(float vlo, float vhi) {
    uint32_t r;
    asm("cvt.rn.bf16x2.f32 %0, %1, %2;" : "=r"(r) : "f"(vhi), "f"(vlo));
    return r;
}
__device__ __forceinline__ void splitbf2(float v0, float v1, uint32_t& hi, uint32_t& lo) {
    hi = packbf2(v0, v1);
    float h0 = __uint_as_float(hi << 16);
    float h1 = __uint_as_float(hi & 0xFFFF0000u);
    lo = packbf2(v0 - h0, v1 - h1);
}
__device__ __forceinline__ uint32_t smem_u32(const void* p) {
    uint32_t a;
    asm("{ .reg .u64 t; cvta.to.shared.u64 t, %1; cvt.u32.u64 %0, t; }" : "=r"(a) : "l"(p));
    return a;
}
__device__ __forceinline__ void cp16(uint32_t dst, const void* src) {
    asm volatile("cp.async.cg.shared.global [%0], [%1], 16;" :: "r"(dst), "l"(src) : "memory");
}
__device__ __forceinline__ void ldsm4(uint32_t r[4], uint32_t addr) {
    asm volatile("ldmatrix.sync.aligned.m8n8.x4.shared.b16 {%0,%1,%2,%3}, [%4];"
                 : "=r"(r[0]), "=r"(r[1]), "=r"(r[2]), "=r"(r[3]) : "r"(addr));
}
__device__ __forceinline__ void mma_bf16(float c[4], const uint32_t a[4], const uint32_t b[2]) {
    asm("mma.sync.aligned.m16n8k16.row.col.f32.bf16.bf16.f32 "
        "{%0,%1,%2,%3}, {%4,%5,%6,%7}, {%8,%9}, {%0,%1,%2,%3};\n"
        : "+f"(c[0]), "+f"(c[1]), "+f"(c[2]), "+f"(c[3])
        : "r"(a[0]), "r"(a[1]), "r"(a[2]), "r"(a[3]), "r"(b[0]), "r"(b[1]));
}

// ---------------------------------------------------------------------------
// Gating MLP (proven since R3).
// ---------------------------------------------------------------------------
__global__ void gating_kernel(const float* __restrict__ z,
                              const void* __restrict__ idx_raw,
                              const float* __restrict__ Wg1, const float* __restrict__ bg1,
                              const float* __restrict__ Wg2, const float* __restrict__ bg2,
                              const float* __restrict__ Wg3, const float* __restrict__ bg3)
{
    __shared__ float bufA[8][128];
    __shared__ float bufB[8][128];
    const int warp = threadIdx.x >> 5;
    const int lane = threadIdx.x & 31;
    const int gwarp = blockIdx.x * 8 + warp;
    const int nwarp = gridDim.x * 8;

    const int* idx32 = (const int*)idx_raw;
    const bool is64 = (idx32[1] == 0);

    for (int row = gwarp; row < BATCH; row += nwarp) {
        const float* zr = z + (size_t)row * DIN;
        for (int k = lane; k < 128; k += 32) {
            int col = is64 ? idx32[2 * k] : idx32[k];
            bufA[warp][k] = zr[col & (DIN - 1)];
        }
        __syncwarp();
        {
            float s0 = bg1[lane * 4 + 0], s1 = bg1[lane * 4 + 1];
            float s2 = bg1[lane * 4 + 2], s3 = bg1[lane * 4 + 3];
            #pragma unroll 8
            for (int k = 0; k < 128; ++k) {
                float xk = bufA[warp][k];
                float4 wv = *(const float4*)(Wg1 + k * 128 + lane * 4);
                s0 = fmaf(xk, wv.x, s0); s1 = fmaf(xk, wv.y, s1);
                s2 = fmaf(xk, wv.z, s2); s3 = fmaf(xk, wv.w, s3);
            }
            bufB[warp][lane * 4 + 0] = eluf(s0);
            bufB[warp][lane * 4 + 1] = eluf(s1);
            bufB[warp][lane * 4 + 2] = eluf(s2);
            bufB[warp][lane * 4 + 3] = eluf(s3);
        }
        __syncwarp();
        {
            float s0 = bg2[lane * 4 + 0], s1 = bg2[lane * 4 + 1];
            float s2 = bg2[lane * 4 + 2], s3 = bg2[lane * 4 + 3];
            #pragma unroll 8
            for (int k = 0; k < 128; ++k) {
                float xk = bufB[warp][k];
                float4 wv = *(const float4*)(Wg2 + k * 128 + lane * 4);
                s0 = fmaf(xk, wv.x, s0); s1 = fmaf(xk, wv.y, s1);
                s2 = fmaf(xk, wv.z, s2); s3 = fmaf(xk, wv.w, s3);
            }
            bufA[warp][lane * 4 + 0] = eluf(s0);
            bufA[warp][lane * 4 + 1] = eluf(s1);
            bufA[warp][lane * 4 + 2] = eluf(s2);
            bufA[warp][lane * 4 + 3] = eluf(s3);
        }
        __syncwarp();
        if (lane < 8) {
            float s = bg3[lane];
            #pragma unroll 8
            for (int k = 0; k < 128; ++k)
                s = fmaf(bufA[warp][k], Wg3[k * 8 + lane], s);
            g_w[(size_t)row * 8 + lane] = s;
        }
        __syncwarp();
    }
}

// ---------------------------------------------------------------------------
// W pre-transpose+split: W[k=4096][o=512] fp32 -> Wt hi/lo [o=512][k=4096] bf16
// ---------------------------------------------------------------------------
__global__ void wsplit_kernel(const float* __restrict__ W, int layer)
{
    __shared__ float T[32][33];
    __nv_bfloat16* oh = g_wth + (size_t)layer * DH * KTOT;
    __nv_bfloat16* ol = g_wtl + (size_t)layer * DH * KTOT;
    const int kt = blockIdx.x * 32, ot = blockIdx.y * 32;
    const int tx = threadIdx.x, ty = threadIdx.y;   // 32 x 8
    #pragma unroll
    for (int i = 0; i < 4; ++i)
        T[ty + 8 * i][tx] = W[(size_t)(kt + ty + 8 * i) * DH + ot + tx];
    __syncthreads();
    #pragma unroll
    for (int i = 0; i < 4; ++i) {
        const int o = ot + ty + 8 * i, k = kt + tx;
        float v = T[tx][ty + 8 * i];
        __nv_bfloat16 h = __float2bfloat16(v);
        oh[(size_t)o * KTOT + k] = h;
        ol[(size_t)o * KTOT + k] = __float2bfloat16(v - __bfloat162float(h));
    }
}

// ---------------------------------------------------------------------------
// z -> split bf16 hi/lo (layer-1 input)
// ---------------------------------------------------------------------------
__global__ void splitz_kernel(const float* __restrict__ z)
{
    const size_t i = (size_t)(blockIdx.x * blockDim.x + threadIdx.x);
    const size_t n4 = (size_t)BATCH * DIN / 4;
    if (i >= n4) return;
    float4 v = ((const float4*)z)[i];
    uint32_t h0, l0, h1, l1;
    splitbf2(v.x, v.y, h0, l0);
    splitbf2(v.z, v.w, h1, l1);
    ((uint2*)g_xah)[i] = make_uint2(h0, h1);
    ((uint2*)g_xal)[i] = make_uint2(l0, l1);
}

// ---------------------------------------------------------------------------
// Layer kernel: CTA 128x128, 512 threads, 16 warps (4m x 4n, warp tile 32x32),
// BK=64, 3-stage swizzled cp.async pipeline (wait_group 1).
// MODE 0: Xa -> Xb split; MODE 1: Xb -> Xa split; MODE 2: Xa -> fp32 out.
// ---------------------------------------------------------------------------
template <bool ACT, int MODE>
__global__ __launch_bounds__(512, 1)
void layer_mm(const float* __restrict__ bias, float* __restrict__ Yp)
{
    const __nv_bfloat16* Xh = (MODE == 1) ? g_xbh : g_xah;
    const __nv_bfloat16* Xl = (MODE == 1) ? g_xbl : g_xal;
    const __nv_bfloat16* Wth = g_wth + (size_t)MODE * DH * KTOT;
    const __nv_bfloat16* Wtl = g_wtl + (size_t)MODE * DH * KTOT;

    extern __shared__ char sm[];
    const uint32_t sb = smem_u32(sm);
    float* wsm = (float*)(sm + WSM_OFF);
    float* bsm = (float*)(sm + BSM_OFF);

    const int tid  = threadIdx.x;
    const int lane = tid & 31;
    const int warp = tid >> 5;
    const int g = lane >> 2, t = lane & 3;
    const int wm = warp >> 2, wn = warp & 3;        // 4 x 4 warps, tile 32x32
    const int mBase = blockIdx.y * BM;
    const int nBase = blockIdx.x * BN;

    for (int i = tid; i < BM * EXPN; i += 512) wsm[i] = g_w[(size_t)mBase * EXPN + i];
    for (int i = tid; i < EXPN * BN; i += 512) bsm[i] = bias[(i >> 7) * DH + nBase + (i & 127)];

    float part[2][4][4], tot[2][4][4];
    #pragma unroll
    for (int mt = 0; mt < 2; ++mt)
        #pragma unroll
        for (int nf = 0; nf < 4; ++nf)
            #pragma unroll
            for (int q = 0; q < 4; ++q) { part[mt][nf][q] = 0.f; tot[mt][nf][q] = 0.f; }

    // ldmatrix per-thread swizzled addressing:
    //   addr = stage + tile + row*128 + ((chunk ^ (row&7)) << 4)
    const int a_row0 = wm * 32 + (lane & 15);               // + mt*16 (mult of 8)
    const int a_ch0  = (lane >> 4) & 1;                      // + ks*2
    const int a_xor  = a_row0 & 7;
    const int b_row0 = wn * 32 + (lane & 7) + ((lane & 16) >> 1);  // + p*16
    const int b_ch0  = (lane >> 3) & 1;
    const int b_xor  = b_row0 & 7;

    // cp.async indices: r = j>>3 (row), c = j&7 (16B chunk)
    const int cp_r = tid >> 3, cp_c = tid & 7;
    const uint32_t cp_d0 = (uint32_t)(cp_r * 128 + ((cp_c ^ (cp_r & 7)) << 4));
    const int cp_r1 = (tid + 512) >> 3, cp_c1 = tid & 7;
    const uint32_t cp_d1 = (uint32_t)(cp_r1 * 128 + ((cp_c1 ^ (cp_r1 & 7)) << 4));

    auto cpAB = [&](int it, int buf) {
        const uint32_t base = sb + buf * STAGE;
        const int i0 = (it & 7) * BK;
        {   // A tiles (rows 0..63 then 64..127)
            const size_t s0 = (size_t)(mBase + cp_r) * DIN + i0 + cp_c * 8;
            const size_t s1 = (size_t)(mBase + cp_r1) * DIN + i0 + cp_c1 * 8;
            cp16(base + cp_d0, Xh + s0);
            cp16(base + OFF_AL + cp_d0, Xl + s0);
            cp16(base + cp_d1, Xh + s1);
            cp16(base + OFF_AL + cp_d1, Xl + s1);
        }
        {   // B tiles
            const size_t ko = (size_t)it * BK;
            const size_t s0 = (size_t)(nBase + cp_r) * KTOT + ko + cp_c * 8;
            const size_t s1 = (size_t)(nBase + cp_r1) * KTOT + ko + cp_c1 * 8;
            cp16(base + OFF_BH + cp_d0, Wth + s0);
            cp16(base + OFF_BL + cp_d0, Wtl + s0);
            cp16(base + OFF_BH + cp_d1, Wth + s1);
            cp16(base + OFF_BL + cp_d1, Wtl + s1);
        }
    };

    // prologue: fill stages 0,1
    cpAB(0, 0);
    asm volatile("cp.async.commit_group;" ::: "memory");
    cpAB(1, 1);
    asm volatile("cp.async.commit_group;" ::: "memory");

    int buf = 0;
    for (int it = 0; it < NIT; ++it) {
        asm volatile("cp.async.wait_group 1;" ::: "memory");
        __syncthreads();

        // refill stage (it+2): overwrites buffer consumed at it-1
        if (it + 2 < NIT) cpAB(it + 2, (it + 2) % NSTAGE);
        asm volatile("cp.async.commit_group;" ::: "memory");   // possibly empty group

        const uint32_t st = sb + buf * STAGE;
        #pragma unroll
        for (int ks = 0; ks < 4; ++ks) {
            uint32_t ah[2][4], al[2][4], bh[2][4], bl[2][4];
            #pragma unroll
            for (int mt = 0; mt < 2; ++mt) {
                uint32_t ao = st + (uint32_t)((a_row0 + mt * 16) * 128)
                            + (uint32_t)((((ks * 2 + a_ch0) ^ a_xor)) << 4);
                ldsm4(ah[mt], ao);
                ldsm4(al[mt], ao + OFF_AL);
            }
            #pragma unroll
            for (int p = 0; p < 2; ++p) {
                uint32_t bo = st + OFF_BH + (uint32_t)((b_row0 + p * 16) * 128)
                            + (uint32_t)((((ks * 2 + b_ch0) ^ b_xor)) << 4);
                ldsm4(bh[p], bo);
                ldsm4(bl[p], bo + TILEB);
            }
            #pragma unroll
            for (int mt = 0; mt < 2; ++mt)
                #pragma unroll
                for (int nf = 0; nf < 4; ++nf)
                    mma_bf16(part[mt][nf], ah[mt], &bh[nf >> 1][(nf & 1) * 2]);
            #pragma unroll
            for (int mt = 0; mt < 2; ++mt)
                #pragma unroll
                for (int nf = 0; nf < 4; ++nf)
                    mma_bf16(part[mt][nf], ah[mt], &bl[nf >> 1][(nf & 1) * 2]);
            #pragma unroll
            for (int mt = 0; mt < 2; ++mt)
                #pragma unroll
                for (int nf = 0; nf < 4; ++nf)
                    mma_bf16(part[mt][nf], al[mt], &bh[nf >> 1][(nf & 1) * 2]);
        }

        if ((it & 7) == 7) {   // expert boundary: fold partial with w_e
            const int e = it >> 3;
            #pragma unroll
            for (int mt = 0; mt < 2; ++mt) {
                const int r0 = wm * 32 + mt * 16 + g;
                const float w0 = wsm[r0 * 8 + e];
                const float w1 = wsm[(r0 + 8) * 8 + e];
                #pragma unroll
                for (int nf = 0; nf < 4; ++nf) {
                    tot[mt][nf][0] = fmaf(w0, part[mt][nf][0], tot[mt][nf][0]);
                    tot[mt][nf][1] = fmaf(w0, part[mt][nf][1], tot[mt][nf][1]);
                    tot[mt][nf][2] = fmaf(w1, part[mt][nf][2], tot[mt][nf][2]);
                    tot[mt][nf][3] = fmaf(w1, part[mt][nf][3], tot[mt][nf][3]);
                    part[mt][nf][0] = 0.f; part[mt][nf][1] = 0.f;
                    part[mt][nf][2] = 0.f; part[mt][nf][3] = 0.f;
                }
            }
        }

        buf = (buf + 1 == NSTAGE) ? 0 : buf + 1;
    }

    // epilogue: + w @ bias, activation, store (split bf16 for MODE<2)
    #pragma unroll
    for (int mt = 0; mt < 2; ++mt) {
        const int r0 = wm * 32 + mt * 16 + g;
        float w0[8], w1[8];
        #pragma unroll
        for (int e = 0; e < 8; ++e) {
            w0[e] = wsm[r0 * 8 + e];
            w1[e] = wsm[(r0 + 8) * 8 + e];
        }
        #pragma unroll
        for (int nf = 0; nf < 4; ++nf) {
            const int c = wn * 32 + nf * 8 + t * 2;
            float b00 = 0.f, b01 = 0.f, b10 = 0.f, b11 = 0.f;
            #pragma unroll
            for (int e = 0; e < 8; ++e) {
                float be0 = bsm[e * 128 + c], be1 = bsm[e * 128 + c + 1];
                b00 = fmaf(w0[e], be0, b00); b01 = fmaf(w0[e], be1, b01);
                b10 = fmaf(w1[e], be0, b10); b11 = fmaf(w1[e], be1, b11);
            }
            float v0 = tot[mt][nf][0] + b00;
            float v1 = tot[mt][nf][1] + b01;
            float v2 = tot[mt][nf][2] + b10;
            float v3 = tot[mt][nf][3] + b11;
            if (ACT) { v0 = eluf(v0); v1 = eluf(v1); v2 = eluf(v2); v3 = eluf(v3); }
            const size_t o0 = (size_t)(mBase + r0) * DH + nBase + c;
            const size_t o1 = (size_t)(mBase + r0 + 8) * DH + nBase + c;
            if (MODE == 2) {
                *(float2*)(Yp + o0) = make_float2(v0, v1);
                *(float2*)(Yp + o1) = make_float2(v2, v3);
            } else {
                __nv_bfloat16* oh = (MODE == 0) ? g_xbh : g_xah;
                __nv_bfloat16* ol = (MODE == 0) ? g_xbl : g_xal;
                uint32_t h0, l0, h1, l1;
                splitbf2(v0, v1, h0, l0);
                splitbf2(v2, v3, h1, l1);
                *(uint32_t*)(oh + o0) = h0;
                *(uint32_t*)(ol + o0) = l0;
                *(uint32_t*)(oh + o1) = h1;
                *(uint32_t*)(ol + o1) = l1;
            }
        }
    }
}

// ---------------------------------------------------------------------------
extern "C" void kernel_launch(void* const* d_in, const int* in_sizes, int n_in,
                              void* d_out, int out_size)
{
    const float* z   = (const float*)d_in[0];
    const void*  idx = (const void*)d_in[1];
    const float* Wg1 = (const float*)d_in[2];
    const float* bg1 = (const float*)d_in[3];
    const float* Wg2 = (const float*)d_in[4];
    const float* bg2 = (const float*)d_in[5];
    const float* Wg3 = (const float*)d_in[6];
    const float* bg3 = (const float*)d_in[7];
    const float* W1  = (const float*)d_in[8];
    const float* b1  = (const float*)d_in[9];
    const float* W2  = (const float*)d_in[10];
    const float* b2  = (const float*)d_in[11];
    const float* W3  = (const float*)d_in[12];
    const float* b3  = (const float*)d_in[13];
    float* out = (float*)d_out;

    cudaFuncSetAttribute(layer_mm<true , 0>, cudaFuncAttributeMaxDynamicSharedMemorySize, SMEM_BYTES);
    cudaFuncSetAttribute(layer_mm<true , 1>, cudaFuncAttributeMaxDynamicSharedMemorySize, SMEM_BYTES);
    cudaFuncSetAttribute(layer_mm<false, 2>, cudaFuncAttributeMaxDynamicSharedMemorySize, SMEM_BYTES);

    gating_kernel<<<1024, 256>>>(z, idx, Wg1, bg1, Wg2, bg2, Wg3, bg3);

    dim3 wgrid(KTOT / 32, DH / 32);   // (128, 16)
    dim3 wblk(32, 8);
    wsplit_kernel<<<wgrid, wblk>>>(W1, 0);
    wsplit_kernel<<<wgrid, wblk>>>(W2, 1);
    wsplit_kernel<<<wgrid, wblk>>>(W3, 2);

    splitz_kernel<<<(BATCH * DIN / 4 + 255) / 256, 256>>>(z);

    dim3 grid(DH / BN, BATCH / BM);   // (4, 512)
    layer_mm<true , 0><<<grid, 512, SMEM_BYTES>>>(b1, nullptr);
    layer_mm<true , 1><<<grid, 512, SMEM_BYTES>>>(b2, nullptr);
    layer_mm<false, 2><<<grid, 512, SMEM_BYTES>>>(b3, out);
}